// round 8
// baseline (speedup 1.0000x reference)
#include <cuda_runtime.h>
#include <cuda_bf16.h>
#include <cstdint>
#include <math_constants.h>

#define CDIM 256
#define KCODES 8192
#define NROWS 16384
#define NT 128              // codes per chunk
#define MT 128              // rows per CTA
#define NCHUNKS (KCODES / NT)
#define CAP 128             // candidate slots per row
#define MARGIN 2.0e-3f      // fp8 screening margin (12.5 sigma)
#define BSCALE 8192.0f      // emb pre-scale into e4m3 range
#define SINV   (2.0f / 8192.0f)
#define GTHREADS 512

// ---------------------------------------------------------------------------
// Device globals (allocation-free scratch)
// ---------------------------------------------------------------------------
__device__ __align__(16) uint8_t g_Aq[(size_t)NROWS * CDIM];    // e4m3(z) [n][c]
__device__ __align__(16) uint8_t g_Bq[(size_t)KCODES * CDIM];   // e4m3(8192*emb) [k][c]
__device__ float    g_A[NROWS];                          // exact ||x||^2 (strict seq)
__device__ float    g_C[KCODES];                         // exact ||e||^2 (strict seq)
__device__ unsigned g_candk[(size_t)NROWS * CAP];
__device__ float    g_cands[(size_t)NROWS * CAP];
__device__ int      g_cnt[NROWS];
__device__ float    g_thresh[NROWS];
__device__ int      g_idx[NROWS];
__device__ float    g_partial[NROWS / 64];

// ---------------------------------------------------------------------------
// Helpers
// ---------------------------------------------------------------------------
__device__ __forceinline__ uint32_t smem_to_u32(const void* p) {
    uint32_t a;
    asm("{ .reg .u64 t; cvta.to.shared.u64 t, %1; cvt.u32.u64 %0, t; }" : "=r"(a) : "l"(p));
    return a;
}
__device__ __forceinline__ unsigned f2ord(float f) {   // order-preserving float->uint
    unsigned u = __float_as_uint(f);
    return (u & 0x80000000u) ? ~u : (u | 0x80000000u);
}
__device__ __forceinline__ float ord2f(unsigned u) {
    return __uint_as_float((u & 0x80000000u) ? (u ^ 0x80000000u) : ~u);
}
__device__ __forceinline__ uint16_t f2_e4m3x2(float hi, float lo) {  // low byte = lo
    uint16_t r;
    asm("cvt.rn.satfinite.e4m3x2.f32 %0, %1, %2;" : "=h"(r) : "f"(hi), "f"(lo));
    return r;
}
__device__ __forceinline__ void ldsm4(uint32_t r[4], uint32_t addr) {
    asm volatile("ldmatrix.sync.aligned.m8n8.x4.shared.b16 {%0,%1,%2,%3}, [%4];"
                 : "=r"(r[0]), "=r"(r[1]), "=r"(r[2]), "=r"(r[3]) : "r"(addr));
}
__device__ __forceinline__ void mma_fp8(float d[4], const uint32_t a[4],
                                        uint32_t b0, uint32_t b1) {
    asm("mma.sync.aligned.m16n8k32.row.col.f32.e4m3.e4m3.f32 "
        "{%0,%1,%2,%3}, {%4,%5,%6,%7}, {%8,%9}, {%0,%1,%2,%3};"
        : "+f"(d[0]), "+f"(d[1]), "+f"(d[2]), "+f"(d[3])
        : "r"(a[0]), "r"(a[1]), "r"(a[2]), "r"(a[3]), "r"(b0), "r"(b1));
}
__device__ __forceinline__ void cp16(uint32_t dst, const void* src) {
    asm volatile("cp.async.cg.shared.global [%0], [%1], 16;" :: "r"(dst), "l"(src) : "memory");
}
#define CP_COMMIT() asm volatile("cp.async.commit_group;" ::: "memory")
#define CP_WAIT0()  asm volatile("cp.async.wait_group 0;" ::: "memory")

// ---------------------------------------------------------------------------
// Prep kernels
// ---------------------------------------------------------------------------
__global__ void conv_a_kernel(const float* __restrict__ z) {   // z[b][c][hw] -> Aq[n][c]
    __shared__ float tile[32][33];
    int b = blockIdx.z, hw0 = blockIdx.x * 32, cb = blockIdx.y * 32;
    int tx = threadIdx.x & 31, ty = threadIdx.x >> 5;
    #pragma unroll
    for (int r = ty; r < 32; r += 8)
        tile[r][tx] = z[((size_t)b * CDIM + cb + r) * 1024 + hw0 + tx];
    __syncthreads();
    #pragma unroll
    for (int r = ty; r < 32; r += 8)
        g_Aq[((size_t)b * 1024 + hw0 + r) * CDIM + cb + tx] =
            (uint8_t)(f2_e4m3x2(0.f, tile[tx][r]) & 0xff);
}

__global__ void conv_b_kernel(const float* __restrict__ emb) {  // e4m3(8192*emb)
    int i = blockIdx.x * blockDim.x + threadIdx.x;   // over KCODES*CDIM/4
    float4 v = ((const float4*)emb)[i];
    uint16_t lo = f2_e4m3x2(v.y * BSCALE, v.x * BSCALE);
    uint16_t hi = f2_e4m3x2(v.w * BSCALE, v.z * BSCALE);
    ((uint32_t*)g_Bq)[i] = (uint32_t)lo | ((uint32_t)hi << 16);
}

// C_k = strict-sequential sum of e^2 (bit-exact), smem-staged for coalescing.
__global__ __launch_bounds__(128)
void c_kernel(const float* __restrict__ emb) {
    __shared__ float tile[128][33];
    const int k0 = blockIdx.x * 128;
    const int tid = threadIdx.x;
    float s = 0.f;
    for (int cb = 0; cb < 8; cb++) {
        __syncthreads();
        for (int u = tid; u < 128 * 32; u += 128) {
            int r = u >> 5, cc = u & 31;   // warp = one 128B row: coalesced
            tile[r][cc] = emb[(size_t)(k0 + r) * CDIM + cb * 32 + cc];
        }
        __syncthreads();
        #pragma unroll
        for (int cc = 0; cc < 32; cc++) {
            float v = tile[tid][cc];
            s = __fadd_rn(s, __fmul_rn(v, v));
        }
    }
    g_C[k0 + tid] = s;
}

// A_n strict-sequential; loads batched 8-wide (MLP), accumulation order unchanged.
__global__ __launch_bounds__(256)
void a_kernel(const float* __restrict__ z) {
    int n = blockIdx.x * blockDim.x + threadIdx.x;
    int b = n >> 10, hw = n & 1023;
    const float* zp = z + (size_t)b * CDIM * 1024 + hw;
    float s = 0.f;
    for (int c0 = 0; c0 < CDIM; c0 += 8) {
        float v[8];
        #pragma unroll
        for (int u = 0; u < 8; u++) v[u] = __ldg(zp + (size_t)(c0 + u) * 1024);
        #pragma unroll
        for (int u = 0; u < 8; u++) s = __fadd_rn(s, __fmul_rn(v[u], v[u]));
    }
    g_A[n] = s;
}

// ---------------------------------------------------------------------------
// FP8 GEMM (QMMA m16n8k32 e4m3) + two-pass screening, cp.async prefetch.
// 512 threads, 16 warps in 4(M) x 4(N) grid, warp tile 32x32.
// Tiles: 128 rows x 256 bytes (e4m3) = 32KB each.
// SMEM layout (bytes): As 0..32K, B0 32K..64K, B1 64K..96K,
//                      C_s 96K (+1KB), runmax (+512), cnt (+512)
// ---------------------------------------------------------------------------
#define SM_A 0
#define SM_B0 32768
#define SM_B1 65536
#define SM_C  98304
#define SM_RMAX (SM_C + 1024)
#define SM_CNT  (SM_RMAX + 512)
#define SM_TOTAL (SM_CNT + 512)

// async-copy 128 rows x 256B gmem->smem, per-row XOR swizzle
// (16B granule g of row r stored at granule g ^ (r&7): conflict-free LDSM)
__device__ __forceinline__ void cp_tile(uint32_t dst, const uint8_t* gsrc, int tid) {
    const char* src = (const char*)gsrc;
    #pragma unroll
    for (int it = 0; it < 4; it++) {
        int u = it * GTHREADS + tid;       // 0..2047 granules of 16B
        int row = u >> 4, gr = u & 15;     // 16 granules (256B) per row
        cp16(dst + row * 256 + ((gr ^ (row & 7)) << 4), src + (size_t)u * 16);
    }
}

__global__ __launch_bounds__(GTHREADS, 1)
void gemm_screen_kernel() {
    extern __shared__ char smem[];
    const uint32_t smem_base = smem_to_u32(smem);
    const int tid = threadIdx.x;
    const int wid = tid >> 5, lane = tid & 31;
    const int wm = wid & 3, wn = wid >> 2;       // 4x4 warp grid
    const int g = lane >> 2, tg = lane & 3;
    const int n0 = blockIdx.x * MT;

    float*    C_s     = (float*)(smem + SM_C);
    unsigned* sh_rmax = (unsigned*)(smem + SM_RMAX);
    int*      sh_cnt  = (int*)(smem + SM_CNT);

    if (tid < 128) { sh_rmax[tid] = f2ord(-CUDART_INF_F); sh_cnt[tid] = 0; }

    // Prologue: async A tile + B chunk 0; C chunk 0 regular
    cp_tile(smem_base + SM_A, g_Aq + (size_t)n0 * CDIM, tid);
    cp_tile(smem_base + SM_B0, g_Bq, tid);
    CP_COMMIT();
    if (tid < 128) C_s[tid] = g_C[tid];
    CP_WAIT0();
    __syncthreads();

    const uint32_t As_base = smem_base + SM_A;

    for (int i = 0; i < NCHUNKS; i++) {
        const int cur = i & 1, nxt = cur ^ 1;

        // Async prefetch next B chunk (+C) — overlaps the whole MMA body
        if (i + 1 < NCHUNKS) {
            cp_tile(smem_base + (nxt ? SM_B1 : SM_B0),
                    g_Bq + (size_t)(i + 1) * NT * CDIM, tid);
            CP_COMMIT();
            if (tid < 128) C_s[nxt * 128 + tid] = g_C[(i + 1) * NT + tid];
        }

        // ---- compute chunk i: warp tile 32(M) x 32(N), K in 8 steps of 32 ----
        const uint32_t Bs_base = smem_base + (cur ? SM_B1 : SM_B0);
        float acc[2][4][4];
        #pragma unroll
        for (int mt = 0; mt < 2; mt++)
            #pragma unroll
            for (int nt = 0; nt < 4; nt++)
                #pragma unroll
                for (int c = 0; c < 4; c++) acc[mt][nt][c] = 0.f;

        #pragma unroll
        for (int ks = 0; ks < 8; ks++) {
            uint32_t a_frag[2][4];
            #pragma unroll
            for (int mt = 0; mt < 2; mt++) {
                int row = wm * 32 + mt * 16 + (lane & 15);
                int gr  = ks * 2 + (lane >> 4);
                ldsm4(a_frag[mt], As_base + row * 256 + ((gr ^ (row & 7)) << 4));
            }
            uint32_t b_frag[2][4];
            #pragma unroll
            for (int bp = 0; bp < 2; bp++) {
                int n  = wn * 32 + bp * 16 + ((lane >> 4) << 3) + (lane & 7);
                int gr = ks * 2 + ((lane >> 3) & 1);
                ldsm4(b_frag[bp], Bs_base + n * 256 + ((gr ^ (n & 7)) << 4));
            }
            #pragma unroll
            for (int mt = 0; mt < 2; mt++)
                #pragma unroll
                for (int bp = 0; bp < 2; bp++) {
                    mma_fp8(acc[mt][bp * 2],     a_frag[mt], b_frag[bp][0], b_frag[bp][1]);
                    mma_fp8(acc[mt][bp * 2 + 1], a_frag[mt], b_frag[bp][2], b_frag[bp][3]);
                }
        }

        // ---- PASS 1: scores (rescaled) in-place + chunk row-max -> sh_rmax ----
        #pragma unroll
        for (int mt = 0; mt < 2; mt++) {
            float lmax[2] = {-CUDART_INF_F, -CUDART_INF_F};
            #pragma unroll
            for (int nt = 0; nt < 4; nt++)
                #pragma unroll
                for (int h = 0; h < 2; h++)
                    #pragma unroll
                    for (int q = 0; q < 2; q++) {
                        int col = wn * 32 + nt * 8 + tg * 2 + q;
                        float s = __fmaf_rn(SINV, acc[mt][nt][h * 2 + q],
                                            -C_s[cur * 128 + col]);
                        acc[mt][nt][h * 2 + q] = s;       // overwrite with score
                        if (s > lmax[h]) lmax[h] = s;
                    }
            #pragma unroll
            for (int h = 0; h < 2; h++) {
                lmax[h] = fmaxf(lmax[h], __shfl_xor_sync(0xffffffffu, lmax[h], 1));
                lmax[h] = fmaxf(lmax[h], __shfl_xor_sync(0xffffffffu, lmax[h], 2));
                if (tg == 0) {
                    int rl = wm * 32 + mt * 16 + h * 8 + g;
                    atomicMax(&sh_rmax[rl], f2ord(lmax[h]));
                }
            }
        }
        __syncthreads();   // runmax now includes this chunk (all wn quarters)

        // ---- PASS 2: insert candidates above updated threshold ----
        const int k0 = i * NT;
        #pragma unroll
        for (int mt = 0; mt < 2; mt++)
            #pragma unroll
            for (int h = 0; h < 2; h++) {
                int rl = wm * 32 + mt * 16 + h * 8 + g;
                float thr = ord2f(sh_rmax[rl]) - MARGIN;
                #pragma unroll
                for (int nt = 0; nt < 4; nt++)
                    #pragma unroll
                    for (int q = 0; q < 2; q++) {
                        float s = acc[mt][nt][h * 2 + q];
                        if (s > thr) {
                            int col = wn * 32 + nt * 8 + tg * 2 + q;
                            int slot = atomicAdd(&sh_cnt[rl], 1);
                            if (slot < CAP) {
                                g_candk[(size_t)(n0 + rl) * CAP + slot] = (unsigned)(k0 + col);
                                g_cands[(size_t)(n0 + rl) * CAP + slot] = s;
                            }
                        }
                    }
            }
        if (i + 1 < NCHUNKS) CP_WAIT0();   // B(i+1) landed during the MMA body
        __syncthreads();
    }

    if (tid < 128) {
        g_cnt[n0 + tid] = sh_cnt[tid];
        g_thresh[n0 + tid] = ord2f(sh_rmax[tid]) - MARGIN;
    }
}

// ---------------------------------------------------------------------------
// Exact reference-emulated distance (validated bit-exact in R2)
// ---------------------------------------------------------------------------
__device__ __forceinline__ float exact_d(const float* __restrict__ zp,
                                         const float* __restrict__ e,
                                         float A, float C) {
    float P = 0.f;
    #pragma unroll 16
    for (int c = 0; c < CDIM; c++)
        P = __fmaf_rn(__ldg(zp + (size_t)c * 1024), __ldg(e + c), P);
    float t = __fsub_rn(A, __fmul_rn(2.0f, P));
    return __fadd_rn(t, C);
}

// One warp per row: exact argmin (first-index tie-break) over candidate set.
__global__ __launch_bounds__(256)
void rescore_kernel(const float* __restrict__ z, const float* __restrict__ emb) {
    const int wid = threadIdx.x >> 5, lane = threadIdx.x & 31;
    const int n = blockIdx.x * 8 + wid;
    const int b = n >> 10, hw = n & 1023;
    const float* zp = z + (size_t)b * CDIM * 1024 + hw;
    const float A = g_A[n];
    const int cnt = g_cnt[n];
    const float thresh = g_thresh[n];

    float bd = CUDART_INF_F;
    int bi = 0x7fffffff;

    if (cnt <= CAP) {
        for (int base = 0; base < cnt; base += 32) {
            int l = base + lane;
            if (l < cnt) {
                float s = g_cands[(size_t)n * CAP + l];
                if (s >= thresh) {
                    int k = (int)g_candk[(size_t)n * CAP + l];
                    float d = exact_d(zp, emb + (size_t)k * CDIM, A, g_C[k]);
                    if (d < bd || (d == bd && k < bi)) { bd = d; bi = k; }
                }
            }
        }
    } else {  // overflow fallback: exact scan of all codes (safety net)
        for (int k = lane; k < KCODES; k += 32) {
            float d = exact_d(zp, emb + (size_t)k * CDIM, A, g_C[k]);
            if (d < bd || (d == bd && k < bi)) { bd = d; bi = k; }
        }
    }
    #pragma unroll
    for (int off = 16; off; off >>= 1) {
        float od = __shfl_down_sync(0xffffffffu, bd, off);
        int   oi = __shfl_down_sync(0xffffffffu, bi, off);
        if (od < bd || (od == bd && oi < bi)) { bd = od; bi = oi; }
    }
    if (lane == 0) g_idx[n] = bi;
}

// ---------------------------------------------------------------------------
// Quantize / losses / indices (validated in R2)
// ---------------------------------------------------------------------------
__global__ __launch_bounds__(256)
void quantize_kernel(const float* __restrict__ z, const float* __restrict__ emb,
                     float* __restrict__ out) {
    __shared__ int bidx_s[64];
    __shared__ float red[256];
    const int tid = threadIdx.x;
    const int n0 = blockIdx.x * 64;
    const int bimg = n0 >> 10, hw0 = n0 & 1023;
    const float* zb = z + (size_t)bimg * CDIM * 1024 + hw0;
    const size_t QELEMS = (size_t)NROWS * CDIM;

    if (tid < 64) {
        int k = g_idx[n0 + tid];
        bidx_s[tid] = k;
        out[QELEMS + 2 + n0 + tid] = (float)k;
    }
    __syncthreads();

    float lsum = 0.f;
    for (int e = tid; e < 64 * CDIM; e += 256) {
        int c = e >> 6, m = e & 63;
        float q  = emb[(size_t)bidx_s[m] * CDIM + c];
        float zv = zb[(size_t)c * 1024 + m];
        float d  = __fsub_rn(q, zv);
        out[(size_t)bimg * CDIM * 1024 + (size_t)c * 1024 + hw0 + m] = __fadd_rn(zv, d);
        lsum = __fmaf_rn(d, d, lsum);
    }
    red[tid] = lsum;
    __syncthreads();
    #pragma unroll
    for (int st = 128; st; st >>= 1) {
        if (tid < st) red[tid] += red[tid + st];
        __syncthreads();
    }
    if (tid == 0) g_partial[blockIdx.x] = red[0];
}

__global__ void finalize_kernel(float* __restrict__ out) {
    __shared__ float red[256];
    red[threadIdx.x] = g_partial[threadIdx.x];
    __syncthreads();
    #pragma unroll
    for (int st = 128; st; st >>= 1) {
        if (threadIdx.x < st) red[threadIdx.x] += red[threadIdx.x + st];
        __syncthreads();
    }
    if (threadIdx.x == 0) {
        const size_t QELEMS = (size_t)NROWS * CDIM;
        float loss = red[0] / (float)QELEMS;
        out[QELEMS]     = loss;
        out[QELEMS + 1] = 0.25f * loss;
    }
}

// ---------------------------------------------------------------------------
extern "C" void kernel_launch(void* const* d_in, const int* in_sizes, int n_in,
                              void* d_out, int out_size) {
    const float* z   = (const float*)d_in[0];
    const float* emb = (const float*)d_in[1];
    float* out = (float*)d_out;

    cudaFuncSetAttribute(gemm_screen_kernel,
                         cudaFuncAttributeMaxDynamicSharedMemorySize, SM_TOTAL);

    conv_a_kernel<<<dim3(32, 8, 16), 256>>>(z);
    conv_b_kernel<<<KCODES * CDIM / 4 / 256, 256>>>(emb);
    c_kernel<<<KCODES / 128, 128>>>(emb);
    a_kernel<<<NROWS / 256, 256>>>(z);
    gemm_screen_kernel<<<NROWS / MT, GTHREADS, SM_TOTAL>>>();
    rescore_kernel<<<NROWS / 8, 256>>>(z, emb);
    quantize_kernel<<<NROWS / 64, 256>>>(z, emb, out);
    finalize_kernel<<<1, 256>>>(out);
}

// round 9
// speedup vs baseline: 10.7485x; 10.7485x over previous
#include <cuda_runtime.h>
#include <cuda_bf16.h>
#include <cstdint>
#include <math_constants.h>

#define CDIM 256
#define KCODES 8192
#define NROWS 16384
#define NT 128              // codes per chunk
#define MT 128              // rows per CTA
#define NCHUNKS (KCODES / NT)
#define CAP 128             // candidate slots per row
#define MARGIN 1.0e-3f      // int8 screening margin (~20 sigma)
#define XSCALE (127.0f / 6.0f)
#define ESCALE (8192.0f * 127.0f)
// s = 2P - C ; P = acc / (XSCALE*ESCALE) -> SINT = 2/(XSCALE*ESCALE)
#define SINT   (12.0f / (127.0f * 127.0f * 8192.0f))
#define GTHREADS 512

// ---------------------------------------------------------------------------
// Device globals (allocation-free scratch)
// ---------------------------------------------------------------------------
__device__ __align__(16) int8_t g_Aq[(size_t)NROWS * CDIM];    // int8(z) [n][c]
__device__ __align__(16) int8_t g_Bq[(size_t)KCODES * CDIM];   // int8(emb) [k][c]
__device__ float    g_A[NROWS];                          // exact ||x||^2 (strict seq)
__device__ float    g_C[KCODES];                         // exact ||e||^2 (strict seq)
__device__ unsigned g_candk[(size_t)NROWS * CAP];
__device__ float    g_cands[(size_t)NROWS * CAP];
__device__ int      g_cnt[NROWS];
__device__ float    g_thresh[NROWS];
__device__ int      g_idx[NROWS];
__device__ float    g_partial[NROWS / 64];

// ---------------------------------------------------------------------------
// Helpers
// ---------------------------------------------------------------------------
__device__ __forceinline__ uint32_t smem_to_u32(const void* p) {
    uint32_t a;
    asm("{ .reg .u64 t; cvta.to.shared.u64 t, %1; cvt.u32.u64 %0, t; }" : "=r"(a) : "l"(p));
    return a;
}
__device__ __forceinline__ unsigned f2ord(float f) {   // order-preserving float->uint
    unsigned u = __float_as_uint(f);
    return (u & 0x80000000u) ? ~u : (u | 0x80000000u);
}
__device__ __forceinline__ float ord2f(unsigned u) {
    return __uint_as_float((u & 0x80000000u) ? (u ^ 0x80000000u) : ~u);
}
__device__ __forceinline__ int q8(float v, float lim, float sc) {
    return __float2int_rn(fminf(fmaxf(v, -lim), lim) * sc);
}
__device__ __forceinline__ void ldsm4(uint32_t r[4], uint32_t addr) {
    asm volatile("ldmatrix.sync.aligned.m8n8.x4.shared.b16 {%0,%1,%2,%3}, [%4];"
                 : "=r"(r[0]), "=r"(r[1]), "=r"(r[2]), "=r"(r[3]) : "r"(addr));
}
__device__ __forceinline__ void mma_s8(int d[4], const uint32_t a[4],
                                       uint32_t b0, uint32_t b1) {
    asm("mma.sync.aligned.m16n8k32.row.col.s32.s8.s8.s32 "
        "{%0,%1,%2,%3}, {%4,%5,%6,%7}, {%8,%9}, {%0,%1,%2,%3};"
        : "+r"(d[0]), "+r"(d[1]), "+r"(d[2]), "+r"(d[3])
        : "r"(a[0]), "r"(a[1]), "r"(a[2]), "r"(a[3]), "r"(b0), "r"(b1));
}
__device__ __forceinline__ void cp16(uint32_t dst, const void* src) {
    asm volatile("cp.async.cg.shared.global [%0], [%1], 16;" :: "r"(dst), "l"(src) : "memory");
}
#define CP_COMMIT() asm volatile("cp.async.commit_group;" ::: "memory")
#define CP_WAIT0()  asm volatile("cp.async.wait_group 0;" ::: "memory")

// ---------------------------------------------------------------------------
// Prep kernels
// ---------------------------------------------------------------------------
__global__ void conv_a_kernel(const float* __restrict__ z) {   // z[b][c][hw] -> Aq[n][c]
    __shared__ float tile[32][33];
    int b = blockIdx.z, hw0 = blockIdx.x * 32, cb = blockIdx.y * 32;
    int tx = threadIdx.x & 31, ty = threadIdx.x >> 5;
    #pragma unroll
    for (int r = ty; r < 32; r += 8)
        tile[r][tx] = z[((size_t)b * CDIM + cb + r) * 1024 + hw0 + tx];
    __syncthreads();
    #pragma unroll
    for (int r = ty; r < 32; r += 8)
        g_Aq[((size_t)b * 1024 + hw0 + r) * CDIM + cb + tx] =
            (int8_t)q8(tile[tx][r], 6.0f, XSCALE);
}

__global__ void conv_b_kernel(const float* __restrict__ emb) {  // int8(emb*8192*127)
    int i = blockIdx.x * blockDim.x + threadIdx.x;   // over KCODES*CDIM/4
    float4 v = ((const float4*)emb)[i];
    int q0 = q8(v.x, 1.0f, ESCALE), q1 = q8(v.y, 1.0f, ESCALE);
    int q2 = q8(v.z, 1.0f, ESCALE), q3 = q8(v.w, 1.0f, ESCALE);
    ((uint32_t*)g_Bq)[i] = (uint32_t)(q0 & 0xff) | ((uint32_t)(q1 & 0xff) << 8) |
                           ((uint32_t)(q2 & 0xff) << 16) | ((uint32_t)(q3 & 0xff) << 24);
}

// C_k = strict-sequential sum of e^2 (bit-exact), smem-staged for coalescing.
__global__ __launch_bounds__(128)
void c_kernel(const float* __restrict__ emb) {
    __shared__ float tile[128][33];
    const int k0 = blockIdx.x * 128;
    const int tid = threadIdx.x;
    float s = 0.f;
    for (int cb = 0; cb < 8; cb++) {
        __syncthreads();
        for (int u = tid; u < 128 * 32; u += 128) {
            int r = u >> 5, cc = u & 31;   // warp = one 128B row: coalesced
            tile[r][cc] = emb[(size_t)(k0 + r) * CDIM + cb * 32 + cc];
        }
        __syncthreads();
        #pragma unroll
        for (int cc = 0; cc < 32; cc++) {
            float v = tile[tid][cc];
            s = __fadd_rn(s, __fmul_rn(v, v));
        }
    }
    g_C[k0 + tid] = s;
}

// A_n strict-sequential; loads batched 8-wide (MLP), accumulation order unchanged.
__global__ __launch_bounds__(256)
void a_kernel(const float* __restrict__ z) {
    int n = blockIdx.x * blockDim.x + threadIdx.x;
    int b = n >> 10, hw = n & 1023;
    const float* zp = z + (size_t)b * CDIM * 1024 + hw;
    float s = 0.f;
    for (int c0 = 0; c0 < CDIM; c0 += 8) {
        float v[8];
        #pragma unroll
        for (int u = 0; u < 8; u++) v[u] = __ldg(zp + (size_t)(c0 + u) * 1024);
        #pragma unroll
        for (int u = 0; u < 8; u++) s = __fadd_rn(s, __fmul_rn(v[u], v[u]));
    }
    g_A[n] = s;
}

// ---------------------------------------------------------------------------
// Int8 GEMM (IMMA m16n8k32) + two-pass screening, cp.async prefetch.
// 512 threads, 16 warps in 4(M) x 4(N) grid, warp tile 32x32.
// Tiles: 128 rows x 256 bytes (int8) = 32KB each.
// SMEM layout (bytes): As 0..32K, B0 32K..64K, B1 64K..96K,
//                      C_s 96K (+1KB), runmax (+512), cnt (+512)
// ---------------------------------------------------------------------------
#define SM_A 0
#define SM_B0 32768
#define SM_B1 65536
#define SM_C  98304
#define SM_RMAX (SM_C + 1024)
#define SM_CNT  (SM_RMAX + 512)
#define SM_TOTAL (SM_CNT + 512)

// async-copy 128 rows x 256B gmem->smem, per-row XOR swizzle
// (16B granule g of row r stored at granule g ^ (r&7): conflict-free LDSM)
__device__ __forceinline__ void cp_tile(uint32_t dst, const int8_t* gsrc, int tid) {
    const char* src = (const char*)gsrc;
    #pragma unroll
    for (int it = 0; it < 4; it++) {
        int u = it * GTHREADS + tid;       // 0..2047 granules of 16B
        int row = u >> 4, gr = u & 15;     // 16 granules (256B) per row
        cp16(dst + row * 256 + ((gr ^ (row & 7)) << 4), src + (size_t)u * 16);
    }
}

__global__ __launch_bounds__(GTHREADS, 1)
void gemm_screen_kernel() {
    extern __shared__ char smem[];
    const uint32_t smem_base = smem_to_u32(smem);
    const int tid = threadIdx.x;
    const int wid = tid >> 5, lane = tid & 31;
    const int wm = wid & 3, wn = wid >> 2;       // 4x4 warp grid
    const int g = lane >> 2, tg = lane & 3;
    const int n0 = blockIdx.x * MT;

    float*    C_s     = (float*)(smem + SM_C);
    unsigned* sh_rmax = (unsigned*)(smem + SM_RMAX);
    int*      sh_cnt  = (int*)(smem + SM_CNT);

    if (tid < 128) { sh_rmax[tid] = f2ord(-CUDART_INF_F); sh_cnt[tid] = 0; }

    // Prologue: async A tile + B chunk 0; C chunk 0 regular
    cp_tile(smem_base + SM_A, g_Aq + (size_t)n0 * CDIM, tid);
    cp_tile(smem_base + SM_B0, g_Bq, tid);
    CP_COMMIT();
    if (tid < 128) C_s[tid] = g_C[tid];
    CP_WAIT0();
    __syncthreads();

    const uint32_t As_base = smem_base + SM_A;

    for (int i = 0; i < NCHUNKS; i++) {
        const int cur = i & 1, nxt = cur ^ 1;

        // Async prefetch next B chunk (+C) — overlaps the whole MMA body
        if (i + 1 < NCHUNKS) {
            cp_tile(smem_base + (nxt ? SM_B1 : SM_B0),
                    g_Bq + (size_t)(i + 1) * NT * CDIM, tid);
            CP_COMMIT();
            if (tid < 128) C_s[nxt * 128 + tid] = g_C[(i + 1) * NT + tid];
        }

        // ---- compute chunk i: warp tile 32(M) x 32(N), K in 8 steps of 32 ----
        const uint32_t Bs_base = smem_base + (cur ? SM_B1 : SM_B0);
        int acc[2][4][4];
        #pragma unroll
        for (int mt = 0; mt < 2; mt++)
            #pragma unroll
            for (int nt = 0; nt < 4; nt++)
                #pragma unroll
                for (int c = 0; c < 4; c++) acc[mt][nt][c] = 0;

        #pragma unroll
        for (int ks = 0; ks < 8; ks++) {
            uint32_t a_frag[2][4];
            #pragma unroll
            for (int mt = 0; mt < 2; mt++) {
                int row = wm * 32 + mt * 16 + (lane & 15);
                int gr  = ks * 2 + (lane >> 4);
                ldsm4(a_frag[mt], As_base + row * 256 + ((gr ^ (row & 7)) << 4));
            }
            uint32_t b_frag[2][4];
            #pragma unroll
            for (int bp = 0; bp < 2; bp++) {
                int n  = wn * 32 + bp * 16 + ((lane >> 4) << 3) + (lane & 7);
                int gr = ks * 2 + ((lane >> 3) & 1);
                ldsm4(b_frag[bp], Bs_base + n * 256 + ((gr ^ (n & 7)) << 4));
            }
            #pragma unroll
            for (int mt = 0; mt < 2; mt++)
                #pragma unroll
                for (int bp = 0; bp < 2; bp++) {
                    mma_s8(acc[mt][bp * 2],     a_frag[mt], b_frag[bp][0], b_frag[bp][1]);
                    mma_s8(acc[mt][bp * 2 + 1], a_frag[mt], b_frag[bp][2], b_frag[bp][3]);
                }
        }

        // ---- PASS 1: scores (rescaled) + chunk row-max -> sh_rmax ----
        float sc[2][4][4];
        #pragma unroll
        for (int mt = 0; mt < 2; mt++) {
            float lmax[2] = {-CUDART_INF_F, -CUDART_INF_F};
            #pragma unroll
            for (int nt = 0; nt < 4; nt++)
                #pragma unroll
                for (int h = 0; h < 2; h++)
                    #pragma unroll
                    for (int q = 0; q < 2; q++) {
                        int col = wn * 32 + nt * 8 + tg * 2 + q;
                        float s = __fmaf_rn(SINT, (float)acc[mt][nt][h * 2 + q],
                                            -C_s[cur * 128 + col]);
                        sc[mt][nt][h * 2 + q] = s;
                        if (s > lmax[h]) lmax[h] = s;
                    }
            #pragma unroll
            for (int h = 0; h < 2; h++) {
                lmax[h] = fmaxf(lmax[h], __shfl_xor_sync(0xffffffffu, lmax[h], 1));
                lmax[h] = fmaxf(lmax[h], __shfl_xor_sync(0xffffffffu, lmax[h], 2));
                if (tg == 0) {
                    int rl = wm * 32 + mt * 16 + h * 8 + g;
                    atomicMax(&sh_rmax[rl], f2ord(lmax[h]));
                }
            }
        }
        __syncthreads();   // runmax now includes this chunk (all wn quarters)

        // ---- PASS 2: insert candidates above updated threshold ----
        const int k0 = i * NT;
        #pragma unroll
        for (int mt = 0; mt < 2; mt++)
            #pragma unroll
            for (int h = 0; h < 2; h++) {
                int rl = wm * 32 + mt * 16 + h * 8 + g;
                float thr = ord2f(sh_rmax[rl]) - MARGIN;
                #pragma unroll
                for (int nt = 0; nt < 4; nt++)
                    #pragma unroll
                    for (int q = 0; q < 2; q++) {
                        float s = sc[mt][nt][h * 2 + q];
                        if (s > thr) {
                            int col = wn * 32 + nt * 8 + tg * 2 + q;
                            int slot = atomicAdd(&sh_cnt[rl], 1);
                            if (slot < CAP) {
                                g_candk[(size_t)(n0 + rl) * CAP + slot] = (unsigned)(k0 + col);
                                g_cands[(size_t)(n0 + rl) * CAP + slot] = s;
                            }
                        }
                    }
            }
        if (i + 1 < NCHUNKS) CP_WAIT0();   // B(i+1) landed during the MMA body
        __syncthreads();
    }

    if (tid < 128) {
        g_cnt[n0 + tid] = sh_cnt[tid];
        g_thresh[n0 + tid] = ord2f(sh_rmax[tid]) - MARGIN;
    }
}

// ---------------------------------------------------------------------------
// Exact reference-emulated distance (validated bit-exact in R2)
// ---------------------------------------------------------------------------
__device__ __forceinline__ float exact_d(const float* __restrict__ zp,
                                         const float* __restrict__ e,
                                         float A, float C) {
    float P = 0.f;
    #pragma unroll 16
    for (int c = 0; c < CDIM; c++)
        P = __fmaf_rn(__ldg(zp + (size_t)c * 1024), __ldg(e + c), P);
    float t = __fsub_rn(A, __fmul_rn(2.0f, P));
    return __fadd_rn(t, C);
}

// One warp per row: exact argmin (first-index tie-break) over candidate set.
__global__ __launch_bounds__(256)
void rescore_kernel(const float* __restrict__ z, const float* __restrict__ emb) {
    const int wid = threadIdx.x >> 5, lane = threadIdx.x & 31;
    const int n = blockIdx.x * 8 + wid;
    const int b = n >> 10, hw = n & 1023;
    const float* zp = z + (size_t)b * CDIM * 1024 + hw;
    const float A = g_A[n];
    const int cnt = g_cnt[n];
    const float thresh = g_thresh[n];

    float bd = CUDART_INF_F;
    int bi = 0x7fffffff;

    if (cnt <= CAP) {
        for (int base = 0; base < cnt; base += 32) {
            int l = base + lane;
            if (l < cnt) {
                float s = g_cands[(size_t)n * CAP + l];
                if (s >= thresh) {
                    int k = (int)g_candk[(size_t)n * CAP + l];
                    float d = exact_d(zp, emb + (size_t)k * CDIM, A, g_C[k]);
                    if (d < bd || (d == bd && k < bi)) { bd = d; bi = k; }
                }
            }
        }
    } else {  // overflow fallback: exact scan of all codes (safety net)
        for (int k = lane; k < KCODES; k += 32) {
            float d = exact_d(zp, emb + (size_t)k * CDIM, A, g_C[k]);
            if (d < bd || (d == bd && k < bi)) { bd = d; bi = k; }
        }
    }
    #pragma unroll
    for (int off = 16; off; off >>= 1) {
        float od = __shfl_down_sync(0xffffffffu, bd, off);
        int   oi = __shfl_down_sync(0xffffffffu, bi, off);
        if (od < bd || (od == bd && oi < bi)) { bd = od; bi = oi; }
    }
    if (lane == 0) g_idx[n] = bi;
}

// ---------------------------------------------------------------------------
// Quantize / losses / indices (validated in R2)
// ---------------------------------------------------------------------------
__global__ __launch_bounds__(256)
void quantize_kernel(const float* __restrict__ z, const float* __restrict__ emb,
                     float* __restrict__ out) {
    __shared__ int bidx_s[64];
    __shared__ float red[256];
    const int tid = threadIdx.x;
    const int n0 = blockIdx.x * 64;
    const int bimg = n0 >> 10, hw0 = n0 & 1023;
    const float* zb = z + (size_t)bimg * CDIM * 1024 + hw0;
    const size_t QELEMS = (size_t)NROWS * CDIM;

    if (tid < 64) {
        int k = g_idx[n0 + tid];
        bidx_s[tid] = k;
        out[QELEMS + 2 + n0 + tid] = (float)k;
    }
    __syncthreads();

    float lsum = 0.f;
    for (int e = tid; e < 64 * CDIM; e += 256) {
        int c = e >> 6, m = e & 63;
        float q  = emb[(size_t)bidx_s[m] * CDIM + c];
        float zv = zb[(size_t)c * 1024 + m];
        float d  = __fsub_rn(q, zv);
        out[(size_t)bimg * CDIM * 1024 + (size_t)c * 1024 + hw0 + m] = __fadd_rn(zv, d);
        lsum = __fmaf_rn(d, d, lsum);
    }
    red[tid] = lsum;
    __syncthreads();
    #pragma unroll
    for (int st = 128; st; st >>= 1) {
        if (tid < st) red[tid] += red[tid + st];
        __syncthreads();
    }
    if (tid == 0) g_partial[blockIdx.x] = red[0];
}

__global__ void finalize_kernel(float* __restrict__ out) {
    __shared__ float red[256];
    red[threadIdx.x] = g_partial[threadIdx.x];
    __syncthreads();
    #pragma unroll
    for (int st = 128; st; st >>= 1) {
        if (threadIdx.x < st) red[threadIdx.x] += red[threadIdx.x + st];
        __syncthreads();
    }
    if (threadIdx.x == 0) {
        const size_t QELEMS = (size_t)NROWS * CDIM;
        float loss = red[0] / (float)QELEMS;
        out[QELEMS]     = loss;
        out[QELEMS + 1] = 0.25f * loss;
    }
}

// ---------------------------------------------------------------------------
extern "C" void kernel_launch(void* const* d_in, const int* in_sizes, int n_in,
                              void* d_out, int out_size) {
    const float* z   = (const float*)d_in[0];
    const float* emb = (const float*)d_in[1];
    float* out = (float*)d_out;

    cudaFuncSetAttribute(gemm_screen_kernel,
                         cudaFuncAttributeMaxDynamicSharedMemorySize, SM_TOTAL);

    conv_a_kernel<<<dim3(32, 8, 16), 256>>>(z);
    conv_b_kernel<<<KCODES * CDIM / 4 / 256, 256>>>(emb);
    c_kernel<<<KCODES / 128, 128>>>(emb);
    a_kernel<<<NROWS / 256, 256>>>(z);
    gemm_screen_kernel<<<NROWS / MT, GTHREADS, SM_TOTAL>>>();
    rescore_kernel<<<NROWS / 8, 256>>>(z, emb);
    quantize_kernel<<<NROWS / 64, 256>>>(z, emb, out);
    finalize_kernel<<<1, 256>>>(out);
}